// round 1
// baseline (speedup 1.0000x reference)
#include <cuda_runtime.h>

// Problem constants
#define BATCH 4
#define SEQ   2048
#define DIN   1024
#define DOUT  1024
#define MTOT  (BATCH * SEQ)          // 8192
#define NEGC  (-1000000000.0f)

// GEMM tiling
#define BM 128
#define BN 128
#define BK 16
#define TM 8
#define TN 8
#define NTHREADS 256
#define PAD 4

// ---------------------------------------------------------------------------
// Scratch (device globals — no allocations allowed)
// ---------------------------------------------------------------------------
__device__ float g_q[(size_t)MTOT * DOUT];              // 32 MB
__device__ float g_k[(size_t)MTOT * DOUT];              // 32 MB
__device__ float g_v[(size_t)MTOT * DOUT];              // 32 MB
__device__ float g_p[(size_t)BATCH * SEQ * SEQ];        // 64 MB (scores -> probs)

// ---------------------------------------------------------------------------
// Kernel 1: fused QKV projection.  out[m,n] = sum_k x[m,k]*W[n,k] + b[n]
// blockIdx.z selects (Wq,bq,g_q) / (Wk,bk,g_k) / (Wv,bv,g_v)
// ---------------------------------------------------------------------------
__global__ __launch_bounds__(NTHREADS) void qkv_kernel(
    const float* __restrict__ x,
    const float* __restrict__ Wq, const float* __restrict__ bq,
    const float* __restrict__ Wk, const float* __restrict__ bk,
    const float* __restrict__ Wv, const float* __restrict__ bv)
{
    const float* W; const float* bias; float* out;
    if (blockIdx.z == 0)      { W = Wq; bias = bq; out = g_q; }
    else if (blockIdx.z == 1) { W = Wk; bias = bk; out = g_k; }
    else                      { W = Wv; bias = bv; out = g_v; }

    const int m0 = blockIdx.y * BM;       // 64 tiles
    const int n0 = blockIdx.x * BN;       // 8 tiles

    __shared__ float As[BK][BM + PAD];
    __shared__ float Bs[BK][BN + PAD];

    const int tid = threadIdx.x;
    const int tm = tid >> 4;              // 0..15
    const int tn = tid & 15;              // 0..15

    float acc[TM][TN];
    #pragma unroll
    for (int i = 0; i < TM; i++)
        #pragma unroll
        for (int j = 0; j < TN; j++) acc[i][j] = 0.0f;

    for (int k0 = 0; k0 < DIN; k0 += BK) {
        #pragma unroll
        for (int it = 0; it < 2; it++) {
            int idx = tid + NTHREADS * it;       // [0,512)
            int row = idx >> 2;                  // 0..127
            int kv  = idx & 3;                   // 0..3
            float4 a = *reinterpret_cast<const float4*>(
                x + (size_t)(m0 + row) * DIN + k0 + kv * 4);
            As[kv*4+0][row] = a.x; As[kv*4+1][row] = a.y;
            As[kv*4+2][row] = a.z; As[kv*4+3][row] = a.w;
            float4 w = *reinterpret_cast<const float4*>(
                W + (size_t)(n0 + row) * DIN + k0 + kv * 4);
            Bs[kv*4+0][row] = w.x; Bs[kv*4+1][row] = w.y;
            Bs[kv*4+2][row] = w.z; Bs[kv*4+3][row] = w.w;
        }
        __syncthreads();
        #pragma unroll
        for (int kk = 0; kk < BK; kk++) {
            float a[TM], b[TN];
            *reinterpret_cast<float4*>(&a[0]) = *reinterpret_cast<const float4*>(&As[kk][tm*TM]);
            *reinterpret_cast<float4*>(&a[4]) = *reinterpret_cast<const float4*>(&As[kk][tm*TM+4]);
            *reinterpret_cast<float4*>(&b[0]) = *reinterpret_cast<const float4*>(&Bs[kk][tn*TN]);
            *reinterpret_cast<float4*>(&b[4]) = *reinterpret_cast<const float4*>(&Bs[kk][tn*TN+4]);
            #pragma unroll
            for (int i = 0; i < TM; i++)
                #pragma unroll
                for (int j = 0; j < TN; j++)
                    acc[i][j] += a[i] * b[j];
        }
        __syncthreads();
    }

    #pragma unroll
    for (int i = 0; i < TM; i++) {
        int m = m0 + tm * TM + i;
        #pragma unroll
        for (int j = 0; j < TN; j++) {
            int n = n0 + tn * TN + j;
            out[(size_t)m * DOUT + n] = acc[i][j] + bias[n];
        }
    }
}

// ---------------------------------------------------------------------------
// Kernel 2: masked scores.  g_p[b,i,j] = q.k/32 + causal + length masks
// Skips tiles strictly above the diagonal (softmax never reads them).
// ---------------------------------------------------------------------------
__global__ __launch_bounds__(NTHREADS) void scores_kernel(const int* __restrict__ lengths)
{
    const int itile = blockIdx.y;
    const int jtile = blockIdx.x;
    if (jtile > itile) return;                 // fully above diagonal
    const int b = blockIdx.z;
    const int m0 = itile * BM;
    const int n0 = jtile * BN;

    __shared__ float As[BK][BM + PAD];
    __shared__ float Bs[BK][BN + PAD];

    const int tid = threadIdx.x;
    const int tm = tid >> 4;
    const int tn = tid & 15;

    const float* qb = g_q + (size_t)b * SEQ * DOUT;
    const float* kb = g_k + (size_t)b * SEQ * DOUT;

    float acc[TM][TN];
    #pragma unroll
    for (int i = 0; i < TM; i++)
        #pragma unroll
        for (int j = 0; j < TN; j++) acc[i][j] = 0.0f;

    for (int k0 = 0; k0 < DOUT; k0 += BK) {
        #pragma unroll
        for (int it = 0; it < 2; it++) {
            int idx = tid + NTHREADS * it;
            int row = idx >> 2;
            int kv  = idx & 3;
            float4 a = *reinterpret_cast<const float4*>(
                qb + (size_t)(m0 + row) * DOUT + k0 + kv * 4);
            As[kv*4+0][row] = a.x; As[kv*4+1][row] = a.y;
            As[kv*4+2][row] = a.z; As[kv*4+3][row] = a.w;
            float4 w = *reinterpret_cast<const float4*>(
                kb + (size_t)(n0 + row) * DOUT + k0 + kv * 4);
            Bs[kv*4+0][row] = w.x; Bs[kv*4+1][row] = w.y;
            Bs[kv*4+2][row] = w.z; Bs[kv*4+3][row] = w.w;
        }
        __syncthreads();
        #pragma unroll
        for (int kk = 0; kk < BK; kk++) {
            float a[TM], bcol[TN];
            *reinterpret_cast<float4*>(&a[0]) = *reinterpret_cast<const float4*>(&As[kk][tm*TM]);
            *reinterpret_cast<float4*>(&a[4]) = *reinterpret_cast<const float4*>(&As[kk][tm*TM+4]);
            *reinterpret_cast<float4*>(&bcol[0]) = *reinterpret_cast<const float4*>(&Bs[kk][tn*TN]);
            *reinterpret_cast<float4*>(&bcol[4]) = *reinterpret_cast<const float4*>(&Bs[kk][tn*TN+4]);
            #pragma unroll
            for (int i = 0; i < TM; i++)
                #pragma unroll
                for (int j = 0; j < TN; j++)
                    acc[i][j] += a[i] * bcol[j];
        }
        __syncthreads();
    }

    const int len = lengths[b];
    float* prow = g_p + (size_t)b * SEQ * SEQ;
    #pragma unroll
    for (int i = 0; i < TM; i++) {
        int gi = m0 + tm * TM + i;
        #pragma unroll
        for (int j = 0; j < TN; j++) {
            int gj = n0 + tn * TN + j;
            float s = acc[i][j] * 0.03125f;          // 1/sqrt(1024), exact
            if (gj > gi) s += NEGC;                  // causal (fp32 add: replicates ref absorption)
            if (gi >= len || gj >= len) s += NEGC;   // length mask
            prow[(size_t)gi * SEQ + gj] = s;
        }
    }
}

// ---------------------------------------------------------------------------
// Kernel 3: row softmax over j in [0, i]; writes exact zeros for j > i.
// ---------------------------------------------------------------------------
__global__ __launch_bounds__(NTHREADS) void softmax_kernel()
{
    const int i = blockIdx.x;
    const int b = blockIdx.y;
    float* row = g_p + ((size_t)b * SEQ + i) * SEQ;
    const int n = i + 1;
    __shared__ float red[NTHREADS];
    const int tid = threadIdx.x;

    float m = -3.4e38f;
    for (int j = tid; j < n; j += NTHREADS) m = fmaxf(m, row[j]);
    red[tid] = m; __syncthreads();
    for (int s = NTHREADS / 2; s > 0; s >>= 1) {
        if (tid < s) red[tid] = fmaxf(red[tid], red[tid + s]);
        __syncthreads();
    }
    m = red[0]; __syncthreads();

    float l = 0.0f;
    for (int j = tid; j < n; j += NTHREADS) l += expf(row[j] - m);
    red[tid] = l; __syncthreads();
    for (int s = NTHREADS / 2; s > 0; s >>= 1) {
        if (tid < s) red[tid] += red[tid + s];
        __syncthreads();
    }
    l = red[0];
    const float r = 1.0f / l;

    for (int j = tid; j < SEQ; j += NTHREADS) {
        float p = 0.0f;
        if (j < n) p = expf(row[j] - m) * r;
        row[j] = p;
    }
}

// ---------------------------------------------------------------------------
// Kernel 4: O = P @ V, K-loop bounded by the causal extent of the row tile.
// ---------------------------------------------------------------------------
__global__ __launch_bounds__(NTHREADS) void pv_kernel(float* __restrict__ out)
{
    const int itile = blockIdx.y;
    const int b = blockIdx.z;
    const int m0 = itile * BM;
    const int n0 = blockIdx.x * BN;
    const int kmax = (itile + 1) * BM;        // columns beyond row tile are exact zeros

    __shared__ float As[BK][BM + PAD];
    __shared__ float Bs[BK][BN + PAD];

    const int tid = threadIdx.x;
    const int tm = tid >> 4;
    const int tn = tid & 15;

    const float* pb = g_p + (size_t)b * SEQ * SEQ;
    const float* vb = g_v + (size_t)b * SEQ * DOUT;

    float acc[TM][TN];
    #pragma unroll
    for (int i = 0; i < TM; i++)
        #pragma unroll
        for (int j = 0; j < TN; j++) acc[i][j] = 0.0f;

    for (int k0 = 0; k0 < kmax; k0 += BK) {
        #pragma unroll
        for (int it = 0; it < 2; it++) {
            int idx = tid + NTHREADS * it;        // [0,512)
            // A tile: 128 rows x 16 k (transpose-store)
            int row = idx >> 2;
            int kv  = idx & 3;
            float4 a = *reinterpret_cast<const float4*>(
                pb + (size_t)(m0 + row) * SEQ + k0 + kv * 4);
            As[kv*4+0][row] = a.x; As[kv*4+1][row] = a.y;
            As[kv*4+2][row] = a.z; As[kv*4+3][row] = a.w;
            // B tile: 16 k-rows x 128 n (direct store)
            int kk = idx >> 5;                    // 0..15
            int nv = idx & 31;                    // 0..31
            float4 w = *reinterpret_cast<const float4*>(
                vb + (size_t)(k0 + kk) * DOUT + n0 + nv * 4);
            *reinterpret_cast<float4*>(&Bs[kk][nv * 4]) = w;
        }
        __syncthreads();
        #pragma unroll
        for (int kk = 0; kk < BK; kk++) {
            float a[TM], bcol[TN];
            *reinterpret_cast<float4*>(&a[0]) = *reinterpret_cast<const float4*>(&As[kk][tm*TM]);
            *reinterpret_cast<float4*>(&a[4]) = *reinterpret_cast<const float4*>(&As[kk][tm*TM+4]);
            *reinterpret_cast<float4*>(&bcol[0]) = *reinterpret_cast<const float4*>(&Bs[kk][tn*TN]);
            *reinterpret_cast<float4*>(&bcol[4]) = *reinterpret_cast<const float4*>(&Bs[kk][tn*TN+4]);
            #pragma unroll
            for (int i = 0; i < TM; i++)
                #pragma unroll
                for (int j = 0; j < TN; j++)
                    acc[i][j] += a[i] * bcol[j];
        }
        __syncthreads();
    }

    #pragma unroll
    for (int i = 0; i < TM; i++) {
        int m = m0 + tm * TM + i;
        #pragma unroll
        for (int j = 0; j < TN; j++) {
            int n = n0 + tn * TN + j;
            out[((size_t)b * SEQ + m) * DOUT + n] = acc[i][j];
        }
    }
}

// ---------------------------------------------------------------------------
extern "C" void kernel_launch(void* const* d_in, const int* in_sizes, int n_in,
                              void* d_out, int out_size)
{
    const float* x  = (const float*)d_in[0];
    const float* Wq = (const float*)d_in[1];
    const float* bq = (const float*)d_in[2];
    const float* Wk = (const float*)d_in[3];
    const float* bk = (const float*)d_in[4];
    const float* Wv = (const float*)d_in[5];
    const float* bv = (const float*)d_in[6];
    const int* lengths = (const int*)d_in[7];
    float* out = (float*)d_out;

    dim3 g1(DOUT / BN, MTOT / BM, 3);          // (8, 64, 3)
    qkv_kernel<<<g1, NTHREADS>>>(x, Wq, bq, Wk, bk, Wv, bv);

    dim3 g2(SEQ / BN, SEQ / BM, BATCH);        // (16, 16, 4)
    scores_kernel<<<g2, NTHREADS>>>(lengths);

    dim3 g3(SEQ, BATCH);                       // (2048, 4)
    softmax_kernel<<<g3, NTHREADS>>>();

    dim3 g4(DOUT / BN, SEQ / BM, BATCH);       // (8, 16, 4)
    pv_kernel<<<g4, NTHREADS>>>(out);
}

// round 3
// speedup vs baseline: 3.0333x; 3.0333x over previous
#include <cuda_runtime.h>
#include <cuda_bf16.h>
#include <cstdint>

#define BATCH 4
#define SEQ   2048
#define DIN   1024
#define DOUT  1024
#define MTOT  (BATCH * SEQ)
#define NEGC  (-1000000000.0f)

// ===========================================================================
// Scratch (device globals — allocations are forbidden)
// ===========================================================================
__device__ __nv_bfloat16 gx_hi[(size_t)MTOT * DIN];
__device__ __nv_bfloat16 gx_lo[(size_t)MTOT * DIN];
__device__ __nv_bfloat16 gw_hi[(size_t)3 * DOUT * DIN];
__device__ __nv_bfloat16 gw_lo[(size_t)3 * DOUT * DIN];
__device__ __nv_bfloat16 gq_hi[(size_t)MTOT * DOUT];
__device__ __nv_bfloat16 gq_lo[(size_t)MTOT * DOUT];
__device__ __nv_bfloat16 gk_hi[(size_t)MTOT * DOUT];
__device__ __nv_bfloat16 gk_lo[(size_t)MTOT * DOUT];
__device__ float         gv_f [(size_t)MTOT * DOUT];
__device__ __nv_bfloat16 gvt_hi[(size_t)BATCH * DOUT * SEQ];
__device__ __nv_bfloat16 gvt_lo[(size_t)BATCH * DOUT * SEQ];
__device__ float         gs_f [(size_t)BATCH * SEQ * SEQ];
__device__ __nv_bfloat16 gp_hi[(size_t)BATCH * SEQ * SEQ];
__device__ __nv_bfloat16 gp_lo[(size_t)BATCH * SEQ * SEQ];

// ===========================================================================
// Base-target PTX helpers (NO tcgen05 — harness compiles for sm_103 base)
// ===========================================================================
__device__ __forceinline__ uint32_t smem_u32(const void* p) {
    uint32_t a;
    asm("{ .reg .u64 t; cvta.to.shared.u64 t, %1; cvt.u32.u64 %0, t; }"
        : "=r"(a) : "l"(p));
    return a;
}

#define CP_ASYNC16(dst, src) \
    asm volatile("cp.async.cg.shared.global [%0], [%1], 16;" \
        :: "r"(dst), "l"(src))
#define CP_COMMIT()  asm volatile("cp.async.commit_group;" ::: "memory")
#define CP_WAIT(N)   asm volatile("cp.async.wait_group %0;" :: "n"(N) : "memory")

__device__ __forceinline__ void ldsm4(uint32_t* r, uint32_t addr) {
    asm volatile("ldmatrix.sync.aligned.m8n8.x4.shared.b16 {%0,%1,%2,%3}, [%4];"
        : "=r"(r[0]), "=r"(r[1]), "=r"(r[2]), "=r"(r[3]) : "r"(addr));
}
__device__ __forceinline__ void ldsm2(uint32_t* r, uint32_t addr) {
    asm volatile("ldmatrix.sync.aligned.m8n8.x2.shared.b16 {%0,%1}, [%2];"
        : "=r"(r[0]), "=r"(r[1]) : "r"(addr));
}

__device__ __forceinline__ void mma_bf16(float* c, const uint32_t* a, const uint32_t* b) {
    asm volatile(
        "mma.sync.aligned.m16n8k16.row.col.f32.bf16.bf16.f32 "
        "{%0,%1,%2,%3}, {%4,%5,%6,%7}, {%8,%9}, {%0,%1,%2,%3};"
        : "+f"(c[0]), "+f"(c[1]), "+f"(c[2]), "+f"(c[3])
        : "r"(a[0]), "r"(a[1]), "r"(a[2]), "r"(a[3]), "r"(b[0]), "r"(b[1]));
}

// ===========================================================================
// Shared GEMM engine: 128x128 CTA tile, 8 warps (2m x 4n), BK=64, 2-stage
// cp.async pipeline, SW128 XOR swizzle, bf16x3 split precision.
// SMEM: per stage: A_hi | A_lo | B_hi | B_lo, each 128 rows x 128B = 16KB.
// ===========================================================================
#define SUB_BYTES   16384
#define STAGE_BYTES 65536
#define SMEM_BYTES  (2 * STAGE_BYTES)    // 131072

__device__ __forceinline__ void fill_stage(
    uint32_t sb, int stage,
    const __nv_bfloat16* aHi, const __nv_bfloat16* aLo, size_t strideA,
    const __nv_bfloat16* bHi, const __nv_bfloat16* bLo, size_t strideB,
    int k0, int tid)
{
    uint32_t base = sb + stage * STAGE_BYTES;
    #pragma unroll
    for (int sub = 0; sub < 4; sub++) {
        const __nv_bfloat16* src = (sub == 0) ? aHi : (sub == 1) ? aLo
                                 : (sub == 2) ? bHi : bLo;
        size_t stride = (sub < 2) ? strideA : strideB;
        uint32_t dst = base + sub * SUB_BYTES;
        #pragma unroll
        for (int t = 0; t < 4; t++) {
            int idx = tid + 256 * t;             // [0,1024)
            int r = idx >> 3;                    // row 0..127
            int c = idx & 7;                     // 16B chunk 0..7
            uint32_t d = dst + (uint32_t)(r * 128 + ((c ^ (r & 7)) << 4));
            const void* g = src + (size_t)r * stride + k0 + c * 8;
            CP_ASYNC16(d, g);
        }
    }
    CP_COMMIT();
}

// Compute one stage (4 k16-steps, 3 split passes) into acc[4][4][4].
__device__ __forceinline__ void compute_stage(
    uint32_t sb, int stage, float acc[4][4][4], int wid, int lane)
{
    uint32_t base = sb + stage * STAGE_BYTES;
    const int wm = (wid & 1) * 64;
    const int wn = (wid >> 1) * 32;
    #pragma unroll
    for (int ks = 0; ks < 4; ks++) {
        uint32_t aH[4][4], aL[4][4], bH[4][2], bL[4][2];
        #pragma unroll
        for (int i = 0; i < 4; i++) {
            int row = wm + i * 16 + (lane & 15);
            int cb  = ks * 2 + (lane >> 4);
            uint32_t ad = base + (uint32_t)(row * 128 + ((cb ^ (row & 7)) << 4));
            ldsm4(aH[i], ad);
            ldsm4(aL[i], ad + SUB_BYTES);
        }
        #pragma unroll
        for (int j = 0; j < 4; j++) {
            int row = wn + j * 8 + (lane & 7);
            int cb  = ks * 2 + ((lane >> 3) & 1);
            uint32_t bd = base + 2 * SUB_BYTES
                        + (uint32_t)(row * 128 + ((cb ^ (row & 7)) << 4));
            ldsm2(bH[j], bd);
            ldsm2(bL[j], bd + SUB_BYTES);
        }
        #pragma unroll
        for (int i = 0; i < 4; i++)
            #pragma unroll
            for (int j = 0; j < 4; j++) {
                mma_bf16(acc[i][j], aH[i], bH[j]);
                mma_bf16(acc[i][j], aH[i], bL[j]);
                mma_bf16(acc[i][j], aL[i], bH[j]);
            }
    }
}

// Full K loop, double-buffered.
__device__ __forceinline__ void gemm_mainloop(
    uint32_t sb, int nch,
    const __nv_bfloat16* aHi, const __nv_bfloat16* aLo, size_t strideA,
    const __nv_bfloat16* bHi, const __nv_bfloat16* bLo, size_t strideB,
    float acc[4][4][4], int tid, int wid, int lane)
{
    fill_stage(sb, 0, aHi, aLo, strideA, bHi, bLo, strideB, 0, tid);
    for (int ch = 0; ch < nch; ch++) {
        if (ch + 1 < nch) {
            fill_stage(sb, (ch + 1) & 1, aHi, aLo, strideA, bHi, bLo, strideB,
                       (ch + 1) * 64, tid);
            CP_WAIT(1);
        } else {
            CP_WAIT(0);
        }
        __syncthreads();
        compute_stage(sb, ch & 1, acc, wid, lane);
        __syncthreads();
    }
}

// ===========================================================================
// Kernel: split fp32 -> bf16 (hi, lo).  dst_id: 0 = x, 1..3 = W[z]
// ===========================================================================
__global__ __launch_bounds__(256) void split_kernel(const float* __restrict__ src,
                                                    int dst_id, int n)
{
    int i = blockIdx.x * 256 + threadIdx.x;
    if (i >= n) return;
    __nv_bfloat16* hi; __nv_bfloat16* lo;
    if (dst_id == 0) { hi = gx_hi; lo = gx_lo; }
    else { size_t off = (size_t)(dst_id - 1) * DOUT * DIN; hi = gw_hi + off; lo = gw_lo + off; }
    float f = src[i];
    __nv_bfloat16 h = __float2bfloat16(f);
    hi[i] = h;
    lo[i] = __float2bfloat16(f - __bfloat162float(h));
}

// ===========================================================================
// Kernel: QKV projection.  z selects Q/K/V.
// ===========================================================================
__global__ __launch_bounds__(256, 1) void qkv_mma(
    const float* __restrict__ bq, const float* __restrict__ bk,
    const float* __restrict__ bv)
{
    extern __shared__ char smem[];
    const uint32_t sb = smem_u32(smem);
    const int tid = threadIdx.x, wid = tid >> 5, lane = tid & 31;
    const int z = blockIdx.z;
    const int m0 = blockIdx.y * 128;
    const int n0 = blockIdx.x * 128;

    const __nv_bfloat16* aHi = gx_hi + (size_t)m0 * DIN;
    const __nv_bfloat16* aLo = gx_lo + (size_t)m0 * DIN;
    size_t woff = (size_t)z * DOUT * DIN + (size_t)n0 * DIN;
    const __nv_bfloat16* bHi = gw_hi + woff;
    const __nv_bfloat16* bLo = gw_lo + woff;
    const float* bias = (z == 0) ? bq : (z == 1) ? bk : bv;

    float acc[4][4][4];
    #pragma unroll
    for (int i = 0; i < 4; i++)
        #pragma unroll
        for (int j = 0; j < 4; j++)
            #pragma unroll
            for (int v = 0; v < 4; v++) acc[i][j][v] = 0.0f;

    gemm_mainloop(sb, DIN / 64, aHi, aLo, DIN, bHi, bLo, DIN, acc, tid, wid, lane);

    const int wm = (wid & 1) * 64, wn = (wid >> 1) * 32;
    #pragma unroll
    for (int i = 0; i < 4; i++) {
        #pragma unroll
        for (int j = 0; j < 4; j++) {
            int col = n0 + wn + j * 8 + (lane & 3) * 2;
            float b0 = bias[col], b1 = bias[col + 1];
            #pragma unroll
            for (int half = 0; half < 2; half++) {
                int m = m0 + wm + i * 16 + (lane >> 2) + half * 8;
                float v0 = acc[i][j][half * 2 + 0] + b0;
                float v1 = acc[i][j][half * 2 + 1] + b1;
                if (z < 2) {
                    __nv_bfloat16 h0 = __float2bfloat16(v0);
                    __nv_bfloat16 h1 = __float2bfloat16(v1);
                    __nv_bfloat16 l0 = __float2bfloat16(v0 - __bfloat162float(h0));
                    __nv_bfloat16 l1 = __float2bfloat16(v1 - __bfloat162float(h1));
                    __nv_bfloat16* oh = (z == 0) ? gq_hi : gk_hi;
                    __nv_bfloat16* ol = (z == 0) ? gq_lo : gk_lo;
                    uint32_t ph, pl;
                    {
                        uint16_t a16 = __bfloat16_as_ushort(h0), b16 = __bfloat16_as_ushort(h1);
                        ph = (uint32_t)a16 | ((uint32_t)b16 << 16);
                        a16 = __bfloat16_as_ushort(l0); b16 = __bfloat16_as_ushort(l1);
                        pl = (uint32_t)a16 | ((uint32_t)b16 << 16);
                    }
                    *reinterpret_cast<uint32_t*>(oh + (size_t)m * DOUT + col) = ph;
                    *reinterpret_cast<uint32_t*>(ol + (size_t)m * DOUT + col) = pl;
                } else {
                    *reinterpret_cast<float2*>(gv_f + (size_t)m * DOUT + col) =
                        make_float2(v0, v1);
                }
            }
        }
    }
}

// ===========================================================================
// Kernel: scores = (Q.K^T)/32 + masks  (skips tiles above diagonal)
// ===========================================================================
__global__ __launch_bounds__(256, 1) void scores_mma(const int* __restrict__ lengths)
{
    if (blockIdx.x > blockIdx.y) return;
    extern __shared__ char smem[];
    const uint32_t sb = smem_u32(smem);
    const int tid = threadIdx.x, wid = tid >> 5, lane = tid & 31;
    const int b = blockIdx.z;
    const int m0 = blockIdx.y * 128;
    const int n0 = blockIdx.x * 128;

    const __nv_bfloat16* aHi = gq_hi + ((size_t)b * SEQ + m0) * DOUT;
    const __nv_bfloat16* aLo = gq_lo + ((size_t)b * SEQ + m0) * DOUT;
    const __nv_bfloat16* bHi = gk_hi + ((size_t)b * SEQ + n0) * DOUT;
    const __nv_bfloat16* bLo = gk_lo + ((size_t)b * SEQ + n0) * DOUT;

    float acc[4][4][4];
    #pragma unroll
    for (int i = 0; i < 4; i++)
        #pragma unroll
        for (int j = 0; j < 4; j++)
            #pragma unroll
            for (int v = 0; v < 4; v++) acc[i][j][v] = 0.0f;

    gemm_mainloop(sb, DOUT / 64, aHi, aLo, DOUT, bHi, bLo, DOUT, acc, tid, wid, lane);

    const int len = lengths[b];
    const int wm = (wid & 1) * 64, wn = (wid >> 1) * 32;
    float* prow = gs_f + (size_t)b * SEQ * SEQ;
    #pragma unroll
    for (int i = 0; i < 4; i++) {
        #pragma unroll
        for (int j = 0; j < 4; j++) {
            int gj = n0 + wn + j * 8 + (lane & 3) * 2;
            #pragma unroll
            for (int half = 0; half < 2; half++) {
                int gi = m0 + wm + i * 16 + (lane >> 2) + half * 8;
                float s0 = acc[i][j][half * 2 + 0] * 0.03125f;
                float s1 = acc[i][j][half * 2 + 1] * 0.03125f;
                bool rowbad = (gi >= len);
                if (gj > gi)            s0 += NEGC;
                if (rowbad || gj >= len)     s0 += NEGC;
                if (gj + 1 > gi)        s1 += NEGC;
                if (rowbad || gj + 1 >= len) s1 += NEGC;
                *reinterpret_cast<float2*>(prow + (size_t)gi * SEQ + gj) =
                    make_float2(s0, s1);
            }
        }
    }
}

// ===========================================================================
// Kernel: row softmax, emits P as bf16 hi/lo (zeros past diagonal up to tile)
// ===========================================================================
__global__ __launch_bounds__(256) void softmax_kernel()
{
    const int i = blockIdx.x;
    const int b = blockIdx.y;
    const float* row = gs_f + ((size_t)b * SEQ + i) * SEQ;
    const int n = i + 1;
    const int nr = ((i >> 7) + 1) << 7;
    __shared__ float red[256];
    const int tid = threadIdx.x;

    float m = -3.4e38f;
    for (int j = tid; j < n; j += 256) m = fmaxf(m, row[j]);
    red[tid] = m; __syncthreads();
    for (int s = 128; s > 0; s >>= 1) {
        if (tid < s) red[tid] = fmaxf(red[tid], red[tid + s]);
        __syncthreads();
    }
    m = red[0]; __syncthreads();

    float l = 0.0f;
    for (int j = tid; j < n; j += 256) l += expf(row[j] - m);
    red[tid] = l; __syncthreads();
    for (int s = 128; s > 0; s >>= 1) {
        if (tid < s) red[tid] += red[tid + s];
        __syncthreads();
    }
    const float r = 1.0f / red[0];

    size_t base = ((size_t)b * SEQ + i) * SEQ;
    for (int j = tid; j < nr; j += 256) {
        float p = (j < n) ? expf(row[j] - m) * r : 0.0f;
        __nv_bfloat16 h = __float2bfloat16(p);
        gp_hi[base + j] = h;
        gp_lo[base + j] = __float2bfloat16(p - __bfloat162float(h));
    }
}

// ===========================================================================
// Kernel: transpose + split V -> Vt (K-major B operand for PV)
// ===========================================================================
__global__ __launch_bounds__(256) void vsplit_kernel()
{
    __shared__ float t[32][33];
    int b = blockIdx.z;
    int n0 = blockIdx.y * 32;
    int j0 = blockIdx.x * 32;
    int tx = threadIdx.x, ty = threadIdx.y;     // (32, 8)
    #pragma unroll
    for (int r = 0; r < 4; r++)
        t[ty + 8 * r][tx] = gv_f[((size_t)b * SEQ + j0 + ty + 8 * r) * DOUT + n0 + tx];
    __syncthreads();
    #pragma unroll
    for (int r = 0; r < 4; r++) {
        int nl = ty + 8 * r;
        float f = t[tx][nl];
        __nv_bfloat16 h = __float2bfloat16(f);
        size_t o = ((size_t)b * DOUT + n0 + nl) * SEQ + j0 + tx;
        gvt_hi[o] = h;
        gvt_lo[o] = __float2bfloat16(f - __bfloat162float(h));
    }
}

// ===========================================================================
// Kernel: O = P @ V  (K bounded by causal extent of the row tile)
// ===========================================================================
__global__ __launch_bounds__(256, 1) void pv_mma(float* __restrict__ out)
{
    extern __shared__ char smem[];
    const uint32_t sb = smem_u32(smem);
    const int tid = threadIdx.x, wid = tid >> 5, lane = tid & 31;
    const int b = blockIdx.z;
    const int itile = blockIdx.y;
    const int m0 = itile * 128;
    const int n0 = blockIdx.x * 128;

    const __nv_bfloat16* aHi = gp_hi + ((size_t)b * SEQ + m0) * SEQ;
    const __nv_bfloat16* aLo = gp_lo + ((size_t)b * SEQ + m0) * SEQ;
    const __nv_bfloat16* bHi = gvt_hi + ((size_t)b * DOUT + n0) * SEQ;
    const __nv_bfloat16* bLo = gvt_lo + ((size_t)b * DOUT + n0) * SEQ;

    float acc[4][4][4];
    #pragma unroll
    for (int i = 0; i < 4; i++)
        #pragma unroll
        for (int j = 0; j < 4; j++)
            #pragma unroll
            for (int v = 0; v < 4; v++) acc[i][j][v] = 0.0f;

    gemm_mainloop(sb, (itile + 1) * 2, aHi, aLo, SEQ, bHi, bLo, SEQ, acc, tid, wid, lane);

    const int wm = (wid & 1) * 64, wn = (wid >> 1) * 32;
    #pragma unroll
    for (int i = 0; i < 4; i++) {
        #pragma unroll
        for (int j = 0; j < 4; j++) {
            int col = n0 + wn + j * 8 + (lane & 3) * 2;
            #pragma unroll
            for (int half = 0; half < 2; half++) {
                int m = m0 + wm + i * 16 + (lane >> 2) + half * 8;
                *reinterpret_cast<float2*>(out + ((size_t)b * SEQ + m) * DOUT + col) =
                    make_float2(acc[i][j][half * 2 + 0], acc[i][j][half * 2 + 1]);
            }
        }
    }
}

// ===========================================================================
extern "C" void kernel_launch(void* const* d_in, const int* in_sizes, int n_in,
                              void* d_out, int out_size)
{
    const float* x  = (const float*)d_in[0];
    const float* Wq = (const float*)d_in[1];
    const float* bq = (const float*)d_in[2];
    const float* Wk = (const float*)d_in[3];
    const float* bk = (const float*)d_in[4];
    const float* Wv = (const float*)d_in[5];
    const float* bv = (const float*)d_in[6];
    const int* lengths = (const int*)d_in[7];
    float* out = (float*)d_out;

    static bool attrs_set = false;
    if (!attrs_set) {
        cudaFuncSetAttribute(qkv_mma,    cudaFuncAttributeMaxDynamicSharedMemorySize, SMEM_BYTES);
        cudaFuncSetAttribute(scores_mma, cudaFuncAttributeMaxDynamicSharedMemorySize, SMEM_BYTES);
        cudaFuncSetAttribute(pv_mma,     cudaFuncAttributeMaxDynamicSharedMemorySize, SMEM_BYTES);
        attrs_set = true;
    }

    const int nx = MTOT * DIN;
    const int nw = DOUT * DIN;
    split_kernel<<<(nx + 255) / 256, 256>>>(x, 0, nx);
    split_kernel<<<(nw + 255) / 256, 256>>>(Wq, 1, nw);
    split_kernel<<<(nw + 255) / 256, 256>>>(Wk, 2, nw);
    split_kernel<<<(nw + 255) / 256, 256>>>(Wv, 3, nw);

    dim3 g1(DOUT / 128, MTOT / 128, 3);                  // (8, 64, 3)
    qkv_mma<<<g1, 256, SMEM_BYTES>>>(bq, bk, bv);

    vsplit_kernel<<<dim3(SEQ / 32, DOUT / 32, BATCH), dim3(32, 8)>>>();

    dim3 g2(SEQ / 128, SEQ / 128, BATCH);                // (16, 16, 4)
    scores_mma<<<g2, 256, SMEM_BYTES>>>(lengths);

    softmax_kernel<<<dim3(SEQ, BATCH), 256>>>();

    dim3 g4(DOUT / 128, SEQ / 128, BATCH);               // (8, 16, 4)
    pv_mma<<<g4, 256, SMEM_BYTES>>>(out);
}

// round 5
// speedup vs baseline: 3.1108x; 1.0256x over previous
#include <cuda_runtime.h>
#include <cuda_bf16.h>
#include <cstdint>

#define BATCH 4
#define SEQ   2048
#define DIN   1024
#define DOUT  1024
#define MTOT  (BATCH * SEQ)
#define NEGC  (-1000000000.0f)

// ===========================================================================
// Scratch (device globals — allocations are forbidden)
// ===========================================================================
__device__ __nv_bfloat16 gx_hi[(size_t)MTOT * DIN];
__device__ __nv_bfloat16 gx_lo[(size_t)MTOT * DIN];
__device__ __nv_bfloat16 gw_hi[(size_t)3 * DOUT * DIN];
__device__ __nv_bfloat16 gw_lo[(size_t)3 * DOUT * DIN];
__device__ __nv_bfloat16 gq_hi[(size_t)MTOT * DOUT];
__device__ __nv_bfloat16 gq_lo[(size_t)MTOT * DOUT];
__device__ __nv_bfloat16 gk_hi[(size_t)MTOT * DOUT];
__device__ __nv_bfloat16 gk_lo[(size_t)MTOT * DOUT];
__device__ float         gv_f [(size_t)MTOT * DOUT];
__device__ __nv_bfloat16 gvt_hi[(size_t)BATCH * DOUT * SEQ];
__device__ __nv_bfloat16 gvt_lo[(size_t)BATCH * DOUT * SEQ];
__device__ float         gs_f [(size_t)BATCH * SEQ * SEQ];
__device__ __nv_bfloat16 gp_hi[(size_t)BATCH * SEQ * SEQ];
__device__ __nv_bfloat16 gp_lo[(size_t)BATCH * SEQ * SEQ];

// ===========================================================================
// Base-target PTX helpers (NO tcgen05 — harness compiles for sm_103 base)
// ===========================================================================
__device__ __forceinline__ uint32_t smem_u32(const void* p) {
    uint32_t a;
    asm("{ .reg .u64 t; cvta.to.shared.u64 t, %1; cvt.u32.u64 %0, t; }"
        : "=r"(a) : "l"(p));
    return a;
}

#define CP_ASYNC16(dst, src) \
    asm volatile("cp.async.cg.shared.global [%0], [%1], 16;" \
        :: "r"(dst), "l"(src))
#define CP_COMMIT()  asm volatile("cp.async.commit_group;" ::: "memory")
#define CP_WAIT(N)   asm volatile("cp.async.wait_group %0;" :: "n"(N) : "memory")

__device__ __forceinline__ void ldsm4(uint32_t* r, uint32_t addr) {
    asm volatile("ldmatrix.sync.aligned.m8n8.x4.shared.b16 {%0,%1,%2,%3}, [%4];"
        : "=r"(r[0]), "=r"(r[1]), "=r"(r[2]), "=r"(r[3]) : "r"(addr));
}

__device__ __forceinline__ void mma_bf16(float* c, const uint32_t* a, const uint32_t* b) {
    asm volatile(
        "mma.sync.aligned.m16n8k16.row.col.f32.bf16.bf16.f32 "
        "{%0,%1,%2,%3}, {%4,%5,%6,%7}, {%8,%9}, {%0,%1,%2,%3};"
        : "+f"(c[0]), "+f"(c[1]), "+f"(c[2]), "+f"(c[3])
        : "r"(a[0]), "r"(a[1]), "r"(a[2]), "r"(a[3]), "r"(b[0]), "r"(b[1]));
}

// ===========================================================================
// Shared GEMM engine: 128x128 CTA tile, 8 warps (2m x 4n), BK=64, 2-stage
// cp.async pipeline, SW128 XOR swizzle, bf16x3 split precision.
// SMEM per stage: A_hi | A_lo | B_hi | B_lo, each 128 rows x 128B = 16KB.
// ===========================================================================
#define SUB_BYTES   16384
#define STAGE_BYTES 65536
#define SMEM_BYTES  (2 * STAGE_BYTES)    // 131072

__device__ __forceinline__ void fill_stage(
    uint32_t sb, int stage,
    const __nv_bfloat16* aHi, const __nv_bfloat16* aLo, size_t strideA,
    const __nv_bfloat16* bHi, const __nv_bfloat16* bLo, size_t strideB,
    int k0, int tid)
{
    uint32_t base = sb + stage * STAGE_BYTES;
    #pragma unroll
    for (int sub = 0; sub < 4; sub++) {
        const __nv_bfloat16* src = (sub == 0) ? aHi : (sub == 1) ? aLo
                                 : (sub == 2) ? bHi : bLo;
        size_t stride = (sub < 2) ? strideA : strideB;
        uint32_t dst = base + sub * SUB_BYTES;
        #pragma unroll
        for (int t = 0; t < 4; t++) {
            int idx = tid + 256 * t;             // [0,1024)
            int r = idx >> 3;                    // row 0..127
            int c = idx & 7;                     // 16B chunk 0..7
            uint32_t d = dst + (uint32_t)(r * 128 + ((c ^ (r & 7)) << 4));
            const void* g = src + (size_t)r * stride + k0 + c * 8;
            CP_ASYNC16(d, g);
        }
    }
    CP_COMMIT();
}

// Compute one stage (4 k16-steps, 3 split passes) into acc[4][4][4].
__device__ __forceinline__ void compute_stage(
    uint32_t sb, int stage, float acc[4][4][4], int wid, int lane)
{
    uint32_t base = sb + stage * STAGE_BYTES;
    const int wm = (wid & 1) * 64;
    const int wn = (wid >> 1) * 32;
    #pragma unroll
    for (int ks = 0; ks < 4; ks++) {
        uint32_t aH[4][4], aL[4][4], bH[4][2], bL[4][2];
        #pragma unroll
        for (int i = 0; i < 4; i++) {
            int row = wm + i * 16 + (lane & 15);
            int cb  = ks * 2 + (lane >> 4);
            uint32_t ad = base + (uint32_t)(row * 128 + ((cb ^ (row & 7)) << 4));
            ldsm4(aH[i], ad);
            ldsm4(aL[i], ad + SUB_BYTES);
        }
        // B: two n-tiles per ldmatrix.x4 (lane groups of 8 pick tile/k-half)
        #pragma unroll
        for (int jp = 0; jp < 2; jp++) {
            int g   = lane >> 3;                         // 0..3
            int row = wn + (jp * 2 + (g >> 1)) * 8 + (lane & 7);
            int cb  = ks * 2 + (g & 1);
            uint32_t bd = base + 2 * SUB_BYTES
                        + (uint32_t)(row * 128 + ((cb ^ (row & 7)) << 4));
            uint32_t t[4];
            ldsm4(t, bd);
            bH[jp*2][0] = t[0]; bH[jp*2][1] = t[1];
            bH[jp*2+1][0] = t[2]; bH[jp*2+1][1] = t[3];
            ldsm4(t, bd + SUB_BYTES);
            bL[jp*2][0] = t[0]; bL[jp*2][1] = t[1];
            bL[jp*2+1][0] = t[2]; bL[jp*2+1][1] = t[3];
        }
        #pragma unroll
        for (int i = 0; i < 4; i++)
            #pragma unroll
            for (int j = 0; j < 4; j++) {
                mma_bf16(acc[i][j], aH[i], bH[j]);
                mma_bf16(acc[i][j], aH[i], bL[j]);
                mma_bf16(acc[i][j], aL[i], bH[j]);
            }
    }
}

// Full K loop, double-buffered.
__device__ __forceinline__ void gemm_mainloop(
    uint32_t sb, int nch,
    const __nv_bfloat16* aHi, const __nv_bfloat16* aLo, size_t strideA,
    const __nv_bfloat16* bHi, const __nv_bfloat16* bLo, size_t strideB,
    float acc[4][4][4], int tid, int wid, int lane)
{
    fill_stage(sb, 0, aHi, aLo, strideA, bHi, bLo, strideB, 0, tid);
    for (int ch = 0; ch < nch; ch++) {
        if (ch + 1 < nch) {
            fill_stage(sb, (ch + 1) & 1, aHi, aLo, strideA, bHi, bLo, strideB,
                       (ch + 1) * 64, tid);
            CP_WAIT(1);
        } else {
            CP_WAIT(0);
        }
        __syncthreads();
        compute_stage(sb, ch & 1, acc, wid, lane);
        __syncthreads();
    }
}

// ===========================================================================
// Kernel: merged split fp32 -> bf16 (hi, lo) for x, Wq, Wk, Wv (one launch)
// ===========================================================================
__global__ __launch_bounds__(256) void split_all_kernel(
    const float* __restrict__ x,  const float* __restrict__ Wq,
    const float* __restrict__ Wk, const float* __restrict__ Wv)
{
    const int nx = MTOT * DIN;
    const int nw = DOUT * DIN;
    int i = blockIdx.x * 256 + threadIdx.x;
    const float* src; __nv_bfloat16 *hi, *lo; int idx;
    if (i < nx) {
        src = x; idx = i; hi = gx_hi; lo = gx_lo;
    } else {
        int t = i - nx;
        int z = t / nw;
        idx = t - z * nw;
        src = (z == 0) ? Wq : (z == 1) ? Wk : Wv;
        hi = gw_hi + (size_t)z * nw;
        lo = gw_lo + (size_t)z * nw;
    }
    float f = src[idx];
    __nv_bfloat16 h = __float2bfloat16(f);
    hi[idx] = h;
    lo[idx] = __float2bfloat16(f - __bfloat162float(h));
}

// ===========================================================================
// Kernel: QKV projection.  z selects Q/K/V.
// ===========================================================================
__global__ __launch_bounds__(256, 1) void qkv_mma(
    const float* __restrict__ bq, const float* __restrict__ bk,
    const float* __restrict__ bv)
{
    extern __shared__ char smem[];
    const uint32_t sb = smem_u32(smem);
    const int tid = threadIdx.x, wid = tid >> 5, lane = tid & 31;
    const int z = blockIdx.z;
    const int m0 = blockIdx.y * 128;
    const int n0 = blockIdx.x * 128;

    const __nv_bfloat16* aHi = gx_hi + (size_t)m0 * DIN;
    const __nv_bfloat16* aLo = gx_lo + (size_t)m0 * DIN;
    size_t woff = (size_t)z * DOUT * DIN + (size_t)n0 * DIN;
    const __nv_bfloat16* bHi = gw_hi + woff;
    const __nv_bfloat16* bLo = gw_lo + woff;
    const float* bias = (z == 0) ? bq : (z == 1) ? bk : bv;

    float acc[4][4][4];
    #pragma unroll
    for (int i = 0; i < 4; i++)
        #pragma unroll
        for (int j = 0; j < 4; j++)
            #pragma unroll
            for (int v = 0; v < 4; v++) acc[i][j][v] = 0.0f;

    gemm_mainloop(sb, DIN / 64, aHi, aLo, DIN, bHi, bLo, DIN, acc, tid, wid, lane);

    const int wm = (wid & 1) * 64, wn = (wid >> 1) * 32;
    #pragma unroll
    for (int i = 0; i < 4; i++) {
        #pragma unroll
        for (int j = 0; j < 4; j++) {
            int col = n0 + wn + j * 8 + (lane & 3) * 2;
            float b0 = bias[col], b1 = bias[col + 1];
            #pragma unroll
            for (int half = 0; half < 2; half++) {
                int m = m0 + wm + i * 16 + (lane >> 2) + half * 8;
                float v0 = acc[i][j][half * 2 + 0] + b0;
                float v1 = acc[i][j][half * 2 + 1] + b1;
                if (z < 2) {
                    __nv_bfloat16 h0 = __float2bfloat16(v0);
                    __nv_bfloat16 h1 = __float2bfloat16(v1);
                    __nv_bfloat16 l0 = __float2bfloat16(v0 - __bfloat162float(h0));
                    __nv_bfloat16 l1 = __float2bfloat16(v1 - __bfloat162float(h1));
                    __nv_bfloat16* oh = (z == 0) ? gq_hi : gk_hi;
                    __nv_bfloat16* ol = (z == 0) ? gq_lo : gk_lo;
                    uint32_t ph, pl;
                    {
                        uint16_t a16 = __bfloat16_as_ushort(h0), b16 = __bfloat16_as_ushort(h1);
                        ph = (uint32_t)a16 | ((uint32_t)b16 << 16);
                        a16 = __bfloat16_as_ushort(l0); b16 = __bfloat16_as_ushort(l1);
                        pl = (uint32_t)a16 | ((uint32_t)b16 << 16);
                    }
                    *reinterpret_cast<uint32_t*>(oh + (size_t)m * DOUT + col) = ph;
                    *reinterpret_cast<uint32_t*>(ol + (size_t)m * DOUT + col) = pl;
                } else {
                    *reinterpret_cast<float2*>(gv_f + (size_t)m * DOUT + col) =
                        make_float2(v0, v1);
                }
            }
        }
    }
}

// ===========================================================================
// Kernel: scores = (Q.K^T)/32 + masks  (skips tiles above diagonal)
// ===========================================================================
__global__ __launch_bounds__(256, 1) void scores_mma(const int* __restrict__ lengths)
{
    if (blockIdx.x > blockIdx.y) return;
    extern __shared__ char smem[];
    const uint32_t sb = smem_u32(smem);
    const int tid = threadIdx.x, wid = tid >> 5, lane = tid & 31;
    const int b = blockIdx.z;
    const int m0 = blockIdx.y * 128;
    const int n0 = blockIdx.x * 128;

    const __nv_bfloat16* aHi = gq_hi + ((size_t)b * SEQ + m0) * DOUT;
    const __nv_bfloat16* aLo = gq_lo + ((size_t)b * SEQ + m0) * DOUT;
    const __nv_bfloat16* bHi = gk_hi + ((size_t)b * SEQ + n0) * DOUT;
    const __nv_bfloat16* bLo = gk_lo + ((size_t)b * SEQ + n0) * DOUT;

    float acc[4][4][4];
    #pragma unroll
    for (int i = 0; i < 4; i++)
        #pragma unroll
        for (int j = 0; j < 4; j++)
            #pragma unroll
            for (int v = 0; v < 4; v++) acc[i][j][v] = 0.0f;

    gemm_mainloop(sb, DOUT / 64, aHi, aLo, DOUT, bHi, bLo, DOUT, acc, tid, wid, lane);

    const int len = lengths[b];
    const int wm = (wid & 1) * 64, wn = (wid >> 1) * 32;
    float* prow = gs_f + (size_t)b * SEQ * SEQ;
    #pragma unroll
    for (int i = 0; i < 4; i++) {
        #pragma unroll
        for (int j = 0; j < 4; j++) {
            int gj = n0 + wn + j * 8 + (lane & 3) * 2;
            #pragma unroll
            for (int half = 0; half < 2; half++) {
                int gi = m0 + wm + i * 16 + (lane >> 2) + half * 8;
                float s0 = acc[i][j][half * 2 + 0] * 0.03125f;
                float s1 = acc[i][j][half * 2 + 1] * 0.03125f;
                bool rowbad = (gi >= len);
                if (gj > gi)                 s0 += NEGC;
                if (rowbad || gj >= len)     s0 += NEGC;
                if (gj + 1 > gi)             s1 += NEGC;
                if (rowbad || gj + 1 >= len) s1 += NEGC;
                *reinterpret_cast<float2*>(prow + (size_t)gi * SEQ + gj) =
                    make_float2(s0, s1);
            }
        }
    }
}

// ===========================================================================
// Kernel: row softmax. Row cached in smem; exp computed once; __expf.
// Emits P as bf16 hi/lo (zeros past diagonal up to tile boundary).
// ===========================================================================
__global__ __launch_bounds__(256) void softmax_kernel()
{
    const int i = blockIdx.x;
    const int b = blockIdx.y;
    const float* row = gs_f + ((size_t)b * SEQ + i) * SEQ;
    const int n = i + 1;
    const int nr = ((i >> 7) + 1) << 7;
    __shared__ float buf[SEQ];
    __shared__ float red[8];
    const int tid = threadIdx.x, lane = tid & 31, wrp = tid >> 5;

    // pass 1: load row into smem, running max
    float m = -3.4e38f;
    for (int j = tid; j < n; j += 256) {
        float v = row[j];
        buf[j] = v;
        m = fmaxf(m, v);
    }
    #pragma unroll
    for (int o = 16; o; o >>= 1) m = fmaxf(m, __shfl_xor_sync(0xFFFFFFFFu, m, o));
    if (lane == 0) red[wrp] = m;
    __syncthreads();
    if (wrp == 0) {
        float t = red[lane & 7];
        #pragma unroll
        for (int o = 4; o; o >>= 1) t = fmaxf(t, __shfl_xor_sync(0xFFFFFFFFu, t, o));
        if (lane == 0) red[0] = t;
    }
    __syncthreads();
    m = red[0];

    // pass 2: exp once into smem, running sum
    float s = 0.0f;
    for (int j = tid; j < n; j += 256) {
        float e = __expf(buf[j] - m);
        buf[j] = e;
        s += e;
    }
    #pragma unroll
    for (int o = 16; o; o >>= 1) s += __shfl_xor_sync(0xFFFFFFFFu, s, o);
    __syncthreads();                      // everyone done reading red[0]
    if (lane == 0) red[wrp] = s;
    __syncthreads();
    if (wrp == 0) {
        float t = red[lane & 7];
        #pragma unroll
        for (int o = 4; o; o >>= 1) t += __shfl_xor_sync(0xFFFFFFFFu, t, o);
        if (lane == 0) red[0] = t;
    }
    __syncthreads();
    const float r = 1.0f / red[0];

    // pass 3: normalize from smem, split-write bf16 hi/lo
    size_t gbase = ((size_t)b * SEQ + i) * SEQ;
    for (int j = tid; j < nr; j += 256) {
        float p = (j < n) ? buf[j] * r : 0.0f;
        __nv_bfloat16 h = __float2bfloat16(p);
        gp_hi[gbase + j] = h;
        gp_lo[gbase + j] = __float2bfloat16(p - __bfloat162float(h));
    }
}

// ===========================================================================
// Kernel: transpose + split V -> Vt (K-major B operand for PV)
// ===========================================================================
__global__ __launch_bounds__(256) void vsplit_kernel()
{
    __shared__ float t[32][33];
    int b = blockIdx.z;
    int n0 = blockIdx.y * 32;
    int j0 = blockIdx.x * 32;
    int tx = threadIdx.x, ty = threadIdx.y;     // (32, 8)
    #pragma unroll
    for (int r = 0; r < 4; r++)
        t[ty + 8 * r][tx] = gv_f[((size_t)b * SEQ + j0 + ty + 8 * r) * DOUT + n0 + tx];
    __syncthreads();
    #pragma unroll
    for (int r = 0; r < 4; r++) {
        int nl = ty + 8 * r;
        float f = t[tx][nl];
        __nv_bfloat16 h = __float2bfloat16(f);
        size_t o = ((size_t)b * DOUT + n0 + nl) * SEQ + j0 + tx;
        gvt_hi[o] = h;
        gvt_lo[o] = __float2bfloat16(f - __bfloat162float(h));
    }
}

// ===========================================================================
// Kernel: O = P @ V  (K bounded by causal extent of the row tile)
// ===========================================================================
__global__ __launch_bounds__(256, 1) void pv_mma(float* __restrict__ out)
{
    extern __shared__ char smem[];
    const uint32_t sb = smem_u32(smem);
    const int tid = threadIdx.x, wid = tid >> 5, lane = tid & 31;
    const int b = blockIdx.z;
    const int itile = blockIdx.y;
    const int m0 = itile * 128;
    const int n0 = blockIdx.x * 128;

    const __nv_bfloat16* aHi = gp_hi + ((size_t)b * SEQ + m0) * SEQ;
    const __nv_bfloat16* aLo = gp_lo + ((size_t)b * SEQ + m0) * SEQ;
    const __nv_bfloat16* bHi = gvt_hi + ((size_t)b * DOUT + n0) * SEQ;
    const __nv_bfloat16* bLo = gvt_lo + ((size_t)b * DOUT + n0) * SEQ;

    float acc[4][4][4];
    #pragma unroll
    for (int i = 0; i < 4; i++)
        #pragma unroll
        for (int j = 0; j < 4; j++)
            #pragma unroll
            for (int v = 0; v < 4; v++) acc[i][j][v] = 0.0f;

    gemm_mainloop(sb, (itile + 1) * 2, aHi, aLo, SEQ, bHi, bLo, SEQ, acc, tid, wid, lane);

    const int wm = (wid & 1) * 64, wn = (wid >> 1) * 32;
    #pragma unroll
    for (int i = 0; i < 4; i++) {
        #pragma unroll
        for (int j = 0; j < 4; j++) {
            int col = n0 + wn + j * 8 + (lane & 3) * 2;
            #pragma unroll
            for (int half = 0; half < 2; half++) {
                int m = m0 + wm + i * 16 + (lane >> 2) + half * 8;
                *reinterpret_cast<float2*>(out + ((size_t)b * SEQ + m) * DOUT + col) =
                    make_float2(acc[i][j][half * 2 + 0], acc[i][j][half * 2 + 1]);
            }
        }
    }
}

// ===========================================================================
extern "C" void kernel_launch(void* const* d_in, const int* in_sizes, int n_in,
                              void* d_out, int out_size)
{
    const float* x  = (const float*)d_in[0];
    const float* Wq = (const float*)d_in[1];
    const float* bq = (const float*)d_in[2];
    const float* Wk = (const float*)d_in[3];
    const float* bk = (const float*)d_in[4];
    const float* Wv = (const float*)d_in[5];
    const float* bv = (const float*)d_in[6];
    const int* lengths = (const int*)d_in[7];
    float* out = (float*)d_out;

    static bool attrs_set = false;
    if (!attrs_set) {
        cudaFuncSetAttribute(qkv_mma,    cudaFuncAttributeMaxDynamicSharedMemorySize, SMEM_BYTES);
        cudaFuncSetAttribute(scores_mma, cudaFuncAttributeMaxDynamicSharedMemorySize, SMEM_BYTES);
        cudaFuncSetAttribute(pv_mma,     cudaFuncAttributeMaxDynamicSharedMemorySize, SMEM_BYTES);
        attrs_set = true;
    }

    // 6 launches per call (ncu -s 5 -c 1 lands on pv_mma of the first call)
    const int ntot = MTOT * DIN + 3 * DOUT * DIN;        // 11534336, /256 exact
    split_all_kernel<<<ntot / 256, 256>>>(x, Wq, Wk, Wv);

    dim3 g1(DOUT / 128, MTOT / 128, 3);                  // (8, 64, 3)
    qkv_mma<<<g1, 256, SMEM_BYTES>>>(bq, bk, bv);

    vsplit_kernel<<<dim3(SEQ / 32, DOUT / 32, BATCH), dim3(32, 8)>>>();

    dim3 g2(SEQ / 128, SEQ / 128, BATCH);                // (16, 16, 4)
    scores_mma<<<g2, 256, SMEM_BYTES>>>(lengths);

    softmax_kernel<<<dim3(SEQ, BATCH), 256>>>();

    dim3 g4(DOUT / 128, SEQ / 128, BATCH);               // (8, 16, 4)
    pv_mma<<<g4, 256, SMEM_BYTES>>>(out);
}

// round 8
// speedup vs baseline: 3.2170x; 1.0342x over previous
#include <cuda_runtime.h>
#include <cuda_bf16.h>
#include <cstdint>

#define BATCH 4
#define SEQ   2048
#define DIN   1024
#define DOUT  1024
#define MTOT  (BATCH * SEQ)
#define NEGC  (-1000000000.0f)

// ===========================================================================
// Scratch (device globals — allocations are forbidden)
// ===========================================================================
__device__ __nv_bfloat16 gx_hi[(size_t)MTOT * DIN];
__device__ __nv_bfloat16 gx_lo[(size_t)MTOT * DIN];
__device__ __nv_bfloat16 gw_hi[(size_t)3 * DOUT * DIN];
__device__ __nv_bfloat16 gw_lo[(size_t)3 * DOUT * DIN];
__device__ __nv_bfloat16 gq_hi[(size_t)MTOT * DOUT];
__device__ __nv_bfloat16 gq_lo[(size_t)MTOT * DOUT];
__device__ __nv_bfloat16 gk_hi[(size_t)MTOT * DOUT];
__device__ __nv_bfloat16 gk_lo[(size_t)MTOT * DOUT];
__device__ float         gv_f [(size_t)MTOT * DOUT];
__device__ __nv_bfloat16 gvt_hi[(size_t)BATCH * DOUT * SEQ];
__device__ __nv_bfloat16 gvt_lo[(size_t)BATCH * DOUT * SEQ];
__device__ float         gs_f [(size_t)BATCH * SEQ * SEQ];
__device__ __nv_bfloat16 gp_hi[(size_t)BATCH * SEQ * SEQ];
__device__ __nv_bfloat16 gp_lo[(size_t)BATCH * SEQ * SEQ];

// ===========================================================================
// Base-target PTX helpers (NO tcgen05 — harness compiles for sm_103 base)
// ===========================================================================
__device__ __forceinline__ uint32_t smem_u32(const void* p) {
    uint32_t a;
    asm("{ .reg .u64 t; cvta.to.shared.u64 t, %1; cvt.u32.u64 %0, t; }"
        : "=r"(a) : "l"(p));
    return a;
}

#define CP_ASYNC16(dst, src) \
    asm volatile("cp.async.cg.shared.global [%0], [%1], 16;" \
        :: "r"(dst), "l"(src))
#define CP_COMMIT()  asm volatile("cp.async.commit_group;" ::: "memory")
#define CP_WAIT(N)   asm volatile("cp.async.wait_group %0;" :: "n"(N) : "memory")

__device__ __forceinline__ void ldsm4(uint32_t* r, uint32_t addr) {
    asm volatile("ldmatrix.sync.aligned.m8n8.x4.shared.b16 {%0,%1,%2,%3}, [%4];"
        : "=r"(r[0]), "=r"(r[1]), "=r"(r[2]), "=r"(r[3]) : "r"(addr));
}

__device__ __forceinline__ void mma_bf16(float* c, const uint32_t* a, const uint32_t* b) {
    asm volatile(
        "mma.sync.aligned.m16n8k16.row.col.f32.bf16.bf16.f32 "
        "{%0,%1,%2,%3}, {%4,%5,%6,%7}, {%8,%9}, {%0,%1,%2,%3};"
        : "+f"(c[0]), "+f"(c[1]), "+f"(c[2]), "+f"(c[3])
        : "r"(a[0]), "r"(a[1]), "r"(a[2]), "r"(a[3]), "r"(b[0]), "r"(b[1]));
}

// ===========================================================================
// Shared GEMM engine: 128x128 CTA tile, 8 warps (2m x 4n), BK=64, 3-stage
// cp.async pipeline, SW128 XOR swizzle, bf16x3 split precision.
// SMEM per stage: A_hi | A_lo | B_hi | B_lo, each 128 rows x 128B = 16KB.
// ===========================================================================
#define SUB_BYTES   16384
#define STAGE_BYTES 65536
#define NSTAGE      3
#define SMEM_BYTES  (NSTAGE * STAGE_BYTES)    // 196608

__device__ __forceinline__ void fill_stage(
    uint32_t sb, int stage,
    const __nv_bfloat16* aHi, const __nv_bfloat16* aLo, size_t strideA,
    const __nv_bfloat16* bHi, const __nv_bfloat16* bLo, size_t strideB,
    int k0, int tid)
{
    uint32_t base = sb + stage * STAGE_BYTES;
    #pragma unroll
    for (int sub = 0; sub < 4; sub++) {
        const __nv_bfloat16* src = (sub == 0) ? aHi : (sub == 1) ? aLo
                                 : (sub == 2) ? bHi : bLo;
        size_t stride = (sub < 2) ? strideA : strideB;
        uint32_t dst = base + sub * SUB_BYTES;
        #pragma unroll
        for (int t = 0; t < 4; t++) {
            int idx = tid + 256 * t;             // [0,1024)
            int r = idx >> 3;                    // row 0..127
            int c = idx & 7;                     // 16B chunk 0..7
            uint32_t d = dst + (uint32_t)(r * 128 + ((c ^ (r & 7)) << 4));
            const void* g = src + (size_t)r * stride + k0 + c * 8;
            CP_ASYNC16(d, g);
        }
    }
    CP_COMMIT();
}

// Compute one stage (4 k16-steps, 3 split passes) into acc[4][4][4].
__device__ __forceinline__ void compute_stage(
    uint32_t sb, int stage, float acc[4][4][4], int wid, int lane)
{
    uint32_t base = sb + stage * STAGE_BYTES;
    const int wm = (wid & 1) * 64;
    const int wn = (wid >> 1) * 32;
    #pragma unroll
    for (int ks = 0; ks < 4; ks++) {
        uint32_t aH[4][4], aL[4][4], bH[4][2], bL[4][2];
        #pragma unroll
        for (int i = 0; i < 4; i++) {
            int row = wm + i * 16 + (lane & 15);
            int cb  = ks * 2 + (lane >> 4);
            uint32_t ad = base + (uint32_t)(row * 128 + ((cb ^ (row & 7)) << 4));
            ldsm4(aH[i], ad);
            ldsm4(aL[i], ad + SUB_BYTES);
        }
        // B: two n-tiles per ldmatrix.x4 (lane groups of 8 pick tile/k-half)
        #pragma unroll
        for (int jp = 0; jp < 2; jp++) {
            int g   = lane >> 3;                         // 0..3
            int row = wn + (jp * 2 + (g >> 1)) * 8 + (lane & 7);
            int cb  = ks * 2 + (g & 1);
            uint32_t bd = base + 2 * SUB_BYTES
                        + (uint32_t)(row * 128 + ((cb ^ (row & 7)) << 4));
            uint32_t t[4];
            ldsm4(t, bd);
            bH[jp*2][0] = t[0]; bH[jp*2][1] = t[1];
            bH[jp*2+1][0] = t[2]; bH[jp*2+1][1] = t[3];
            ldsm4(t, bd + SUB_BYTES);
            bL[jp*2][0] = t[0]; bL[jp*2][1] = t[1];
            bL[jp*2+1][0] = t[2]; bL[jp*2+1][1] = t[3];
        }
        #pragma unroll
        for (int i = 0; i < 4; i++)
            #pragma unroll
            for (int j = 0; j < 4; j++) {
                mma_bf16(acc[i][j], aH[i], bH[j]);
                mma_bf16(acc[i][j], aH[i], bL[j]);
                mma_bf16(acc[i][j], aL[i], bH[j]);
            }
    }
}

// Full K loop, 3-stage pipeline, one barrier per iteration.
// Order per iteration: wait(stage ch ready) -> sync -> compute(ch) ->
// fill(ch+2).  fill(ch+2) targets the buffer last read in iteration ch-1;
// every warp passed this iteration's barrier after finishing ch-1, so the
// refill is race-free while other warps still compute stage ch.
__device__ __forceinline__ void gemm_mainloop(
    uint32_t sb, int nch,
    const __nv_bfloat16* aHi, const __nv_bfloat16* aLo, size_t strideA,
    const __nv_bfloat16* bHi, const __nv_bfloat16* bLo, size_t strideB,
    float acc[4][4][4], int tid, int wid, int lane)
{
    fill_stage(sb, 0, aHi, aLo, strideA, bHi, bLo, strideB, 0, tid);
    if (nch > 1)
        fill_stage(sb, 1, aHi, aLo, strideA, bHi, bLo, strideB, 64, tid);

    int stage = 0;
    for (int ch = 0; ch < nch; ch++) {
        if (ch + 1 < nch) CP_WAIT(1); else CP_WAIT(0);
        __syncthreads();
        compute_stage(sb, stage, acc, wid, lane);
        int nf = ch + 2;
        if (nf < nch) {
            int fs = stage + 2; if (fs >= NSTAGE) fs -= NSTAGE;
            fill_stage(sb, fs, aHi, aLo, strideA, bHi, bLo, strideB, nf * 64, tid);
        }
        if (++stage == NSTAGE) stage = 0;
    }
}

// ===========================================================================
// Kernel: merged split fp32 -> bf16 (hi, lo) for x, Wq, Wk, Wv (one launch)
// ===========================================================================
__global__ __launch_bounds__(256) void split_all_kernel(
    const float* __restrict__ x,  const float* __restrict__ Wq,
    const float* __restrict__ Wk, const float* __restrict__ Wv)
{
    const int nx = MTOT * DIN;
    const int nw = DOUT * DIN;
    int i = blockIdx.x * 256 + threadIdx.x;
    const float* src; __nv_bfloat16 *hi, *lo; int idx;
    if (i < nx) {
        src = x; idx = i; hi = gx_hi; lo = gx_lo;
    } else {
        int t = i - nx;
        int z = t / nw;
        idx = t - z * nw;
        src = (z == 0) ? Wq : (z == 1) ? Wk : Wv;
        hi = gw_hi + (size_t)z * nw;
        lo = gw_lo + (size_t)z * nw;
    }
    float f = src[idx];
    __nv_bfloat16 h = __float2bfloat16(f);
    hi[idx] = h;
    lo[idx] = __float2bfloat16(f - __bfloat162float(h));
}

// ===========================================================================
// Kernel: QKV projection.  z selects Q/K/V.
// ===========================================================================
__global__ __launch_bounds__(256, 1) void qkv_mma(
    const float* __restrict__ bq, const float* __restrict__ bk,
    const float* __restrict__ bv)
{
    extern __shared__ char smem[];
    const uint32_t sb = smem_u32(smem);
    const int tid = threadIdx.x, wid = tid >> 5, lane = tid & 31;
    const int z = blockIdx.z;
    const int m0 = blockIdx.y * 128;
    const int n0 = blockIdx.x * 128;

    const __nv_bfloat16* aHi = gx_hi + (size_t)m0 * DIN;
    const __nv_bfloat16* aLo = gx_lo + (size_t)m0 * DIN;
    size_t woff = (size_t)z * DOUT * DIN + (size_t)n0 * DIN;
    const __nv_bfloat16* bHi = gw_hi + woff;
    const __nv_bfloat16* bLo = gw_lo + woff;
    const float* bias = (z == 0) ? bq : (z == 1) ? bk : bv;

    float acc[4][4][4];
    #pragma unroll
    for (int i = 0; i < 4; i++)
        #pragma unroll
        for (int j = 0; j < 4; j++)
            #pragma unroll
            for (int v = 0; v < 4; v++) acc[i][j][v] = 0.0f;

    gemm_mainloop(sb, DIN / 64, aHi, aLo, DIN, bHi, bLo, DIN, acc, tid, wid, lane);

    const int wm = (wid & 1) * 64, wn = (wid >> 1) * 32;
    #pragma unroll
    for (int i = 0; i < 4; i++) {
        #pragma unroll
        for (int j = 0; j < 4; j++) {
            int col = n0 + wn + j * 8 + (lane & 3) * 2;
            float b0 = bias[col], b1 = bias[col + 1];
            #pragma unroll
            for (int half = 0; half < 2; half++) {
                int m = m0 + wm + i * 16 + (lane >> 2) + half * 8;
                float v0 = acc[i][j][half * 2 + 0] + b0;
                float v1 = acc[i][j][half * 2 + 1] + b1;
                if (z < 2) {
                    __nv_bfloat16 h0 = __float2bfloat16(v0);
                    __nv_bfloat16 h1 = __float2bfloat16(v1);
                    __nv_bfloat16 l0 = __float2bfloat16(v0 - __bfloat162float(h0));
                    __nv_bfloat16 l1 = __float2bfloat16(v1 - __bfloat162float(h1));
                    __nv_bfloat16* oh = (z == 0) ? gq_hi : gk_hi;
                    __nv_bfloat16* ol = (z == 0) ? gq_lo : gk_lo;
                    uint32_t ph, pl;
                    {
                        uint16_t a16 = __bfloat16_as_ushort(h0), b16 = __bfloat16_as_ushort(h1);
                        ph = (uint32_t)a16 | ((uint32_t)b16 << 16);
                        a16 = __bfloat16_as_ushort(l0); b16 = __bfloat16_as_ushort(l1);
                        pl = (uint32_t)a16 | ((uint32_t)b16 << 16);
                    }
                    *reinterpret_cast<uint32_t*>(oh + (size_t)m * DOUT + col) = ph;
                    *reinterpret_cast<uint32_t*>(ol + (size_t)m * DOUT + col) = pl;
                } else {
                    *reinterpret_cast<float2*>(gv_f + (size_t)m * DOUT + col) =
                        make_float2(v0, v1);
                }
            }
        }
    }
}

// ===========================================================================
// Kernel: scores = (Q.K^T)/32 + masks  (skips tiles above diagonal)
// ===========================================================================
__global__ __launch_bounds__(256, 1) void scores_mma(const int* __restrict__ lengths)
{
    if (blockIdx.x > blockIdx.y) return;
    extern __shared__ char smem[];
    const uint32_t sb = smem_u32(smem);
    const int tid = threadIdx.x, wid = tid >> 5, lane = tid & 31;
    const int b = blockIdx.z;
    const int m0 = blockIdx.y * 128;
    const int n0 = blockIdx.x * 128;

    const __nv_bfloat16* aHi = gq_hi + ((size_t)b * SEQ + m0) * DOUT;
    const __nv_bfloat16* aLo = gq_lo + ((size_t)b * SEQ + m0) * DOUT;
    const __nv_bfloat16* bHi = gk_hi + ((size_t)b * SEQ + n0) * DOUT;
    const __nv_bfloat16* bLo = gk_lo + ((size_t)b * SEQ + n0) * DOUT;

    float acc[4][4][4];
    #pragma unroll
    for (int i = 0; i < 4; i++)
        #pragma unroll
        for (int j = 0; j < 4; j++)
            #pragma unroll
            for (int v = 0; v < 4; v++) acc[i][j][v] = 0.0f;

    gemm_mainloop(sb, DOUT / 64, aHi, aLo, DOUT, bHi, bLo, DOUT, acc, tid, wid, lane);

    const int len = lengths[b];
    const int wm = (wid & 1) * 64, wn = (wid >> 1) * 32;
    float* prow = gs_f + (size_t)b * SEQ * SEQ;
    #pragma unroll
    for (int i = 0; i < 4; i++) {
        #pragma unroll
        for (int j = 0; j < 4; j++) {
            int gj = n0 + wn + j * 8 + (lane & 3) * 2;
            #pragma unroll
            for (int half = 0; half < 2; half++) {
                int gi = m0 + wm + i * 16 + (lane >> 2) + half * 8;
                float s0 = acc[i][j][half * 2 + 0] * 0.03125f;
                float s1 = acc[i][j][half * 2 + 1] * 0.03125f;
                bool rowbad = (gi >= len);
                if (gj > gi)                 s0 += NEGC;
                if (rowbad || gj >= len)     s0 += NEGC;
                if (gj + 1 > gi)             s1 += NEGC;
                if (rowbad || gj + 1 >= len) s1 += NEGC;
                *reinterpret_cast<float2*>(prow + (size_t)gi * SEQ + gj) =
                    make_float2(s0, s1);
            }
        }
    }
}

// ===========================================================================
// Kernel: row softmax. Row cached in smem; exp computed once; __expf.
// Emits P as bf16 hi/lo (zeros past diagonal up to tile boundary).
// ===========================================================================
__global__ __launch_bounds__(256) void softmax_kernel()
{
    const int i = blockIdx.x;
    const int b = blockIdx.y;
    const float* row = gs_f + ((size_t)b * SEQ + i) * SEQ;
    const int n = i + 1;
    const int nr = ((i >> 7) + 1) << 7;
    __shared__ float buf[SEQ];
    __shared__ float red[8];
    const int tid = threadIdx.x, lane = tid & 31, wrp = tid >> 5;

    float m = -3.4e38f;
    for (int j = tid; j < n; j += 256) {
        float v = row[j];
        buf[j] = v;
        m = fmaxf(m, v);
    }
    #pragma unroll
    for (int o = 16; o; o >>= 1) m = fmaxf(m, __shfl_xor_sync(0xFFFFFFFFu, m, o));
    if (lane == 0) red[wrp] = m;
    __syncthreads();
    if (wrp == 0) {
        float t = red[lane & 7];
        #pragma unroll
        for (int o = 4; o; o >>= 1) t = fmaxf(t, __shfl_xor_sync(0xFFFFFFFFu, t, o));
        if (lane == 0) red[0] = t;
    }
    __syncthreads();
    m = red[0];

    float s = 0.0f;
    for (int j = tid; j < n; j += 256) {
        float e = __expf(buf[j] - m);
        buf[j] = e;
        s += e;
    }
    #pragma unroll
    for (int o = 16; o; o >>= 1) s += __shfl_xor_sync(0xFFFFFFFFu, s, o);
    __syncthreads();
    if (lane == 0) red[wrp] = s;
    __syncthreads();
    if (wrp == 0) {
        float t = red[lane & 7];
        #pragma unroll
        for (int o = 4; o; o >>= 1) t += __shfl_xor_sync(0xFFFFFFFFu, t, o);
        if (lane == 0) red[0] = t;
    }
    __syncthreads();
    const float r = 1.0f / red[0];

    size_t gbase = ((size_t)b * SEQ + i) * SEQ;
    for (int j = tid; j < nr; j += 256) {
        float p = (j < n) ? buf[j] * r : 0.0f;
        __nv_bfloat16 h = __float2bfloat16(p);
        gp_hi[gbase + j] = h;
        gp_lo[gbase + j] = __float2bfloat16(p - __bfloat162float(h));
    }
}

// ===========================================================================
// Kernel: transpose + split V -> Vt (K-major B operand for PV)
// ===========================================================================
__global__ __launch_bounds__(256) void vsplit_kernel()
{
    __shared__ float t[32][33];
    int b = blockIdx.z;
    int n0 = blockIdx.y * 32;
    int j0 = blockIdx.x * 32;
    int tx = threadIdx.x, ty = threadIdx.y;     // (32, 8)
    #pragma unroll
    for (int r = 0; r < 4; r++)
        t[ty + 8 * r][tx] = gv_f[((size_t)b * SEQ + j0 + ty + 8 * r) * DOUT + n0 + tx];
    __syncthreads();
    #pragma unroll
    for (int r = 0; r < 4; r++) {
        int nl = ty + 8 * r;
        float f = t[tx][nl];
        __nv_bfloat16 h = __float2bfloat16(f);
        size_t o = ((size_t)b * DOUT + n0 + nl) * SEQ + j0 + tx;
        gvt_hi[o] = h;
        gvt_lo[o] = __float2bfloat16(f - __bfloat162float(h));
    }
}

// ===========================================================================
// Kernel: O = P @ V  (K bounded by causal extent of the row tile)
// ===========================================================================
__global__ __launch_bounds__(256, 1) void pv_mma(float* __restrict__ out)
{
    extern __shared__ char smem[];
    const uint32_t sb = smem_u32(smem);
    const int tid = threadIdx.x, wid = tid >> 5, lane = tid & 31;
    const int b = blockIdx.z;
    const int itile = blockIdx.y;
    const int m0 = itile * 128;
    const int n0 = blockIdx.x * 128;

    const __nv_bfloat16* aHi = gp_hi + ((size_t)b * SEQ + m0) * SEQ;
    const __nv_bfloat16* aLo = gp_lo + ((size_t)b * SEQ + m0) * SEQ;
    const __nv_bfloat16* bHi = gvt_hi + ((size_t)b * DOUT + n0) * SEQ;
    const __nv_bfloat16* bLo = gvt_lo + ((size_t)b * DOUT + n0) * SEQ;

    float acc[4][4][4];
    #pragma unroll
    for (int i = 0; i < 4; i++)
        #pragma unroll
        for (int j = 0; j < 4; j++)
            #pragma unroll
            for (int v = 0; v < 4; v++) acc[i][j][v] = 0.0f;

    gemm_mainloop(sb, (itile + 1) * 2, aHi, aLo, SEQ, bHi, bLo, SEQ, acc, tid, wid, lane);

    const int wm = (wid & 1) * 64, wn = (wid >> 1) * 32;
    #pragma unroll
    for (int i = 0; i < 4; i++) {
        #pragma unroll
        for (int j = 0; j < 4; j++) {
            int col = n0 + wn + j * 8 + (lane & 3) * 2;
            #pragma unroll
            for (int half = 0; half < 2; half++) {
                int m = m0 + wm + i * 16 + (lane >> 2) + half * 8;
                *reinterpret_cast<float2*>(out + ((size_t)b * SEQ + m) * DOUT + col) =
                    make_float2(acc[i][j][half * 2 + 0], acc[i][j][half * 2 + 1]);
            }
        }
    }
}

// ===========================================================================
extern "C" void kernel_launch(void* const* d_in, const int* in_sizes, int n_in,
                              void* d_out, int out_size)
{
    const float* x  = (const float*)d_in[0];
    const float* Wq = (const float*)d_in[1];
    const float* bq = (const float*)d_in[2];
    const float* Wk = (const float*)d_in[3];
    const float* bk = (const float*)d_in[4];
    const float* Wv = (const float*)d_in[5];
    const float* bv = (const float*)d_in[6];
    const int* lengths = (const int*)d_in[7];
    float* out = (float*)d_out;

    static bool attrs_set = false;
    if (!attrs_set) {
        cudaFuncSetAttribute(qkv_mma,    cudaFuncAttributeMaxDynamicSharedMemorySize, SMEM_BYTES);
        cudaFuncSetAttribute(scores_mma, cudaFuncAttributeMaxDynamicSharedMemorySize, SMEM_BYTES);
        cudaFuncSetAttribute(pv_mma,     cudaFuncAttributeMaxDynamicSharedMemorySize, SMEM_BYTES);
        attrs_set = true;
    }

    const int ntot = MTOT * DIN + 3 * DOUT * DIN;        // 11534336, /256 exact
    split_all_kernel<<<ntot / 256, 256>>>(x, Wq, Wk, Wv);

    dim3 g1(DOUT / 128, MTOT / 128, 3);                  // (8, 64, 3)
    qkv_mma<<<g1, 256, SMEM_BYTES>>>(bq, bk, bv);

    vsplit_kernel<<<dim3(SEQ / 32, DOUT / 32, BATCH), dim3(32, 8)>>>();

    dim3 g2(SEQ / 128, SEQ / 128, BATCH);                // (16, 16, 4)
    scores_mma<<<g2, 256, SMEM_BYTES>>>(lengths);

    softmax_kernel<<<dim3(SEQ, BATCH), 256>>>();

    dim3 g4(DOUT / 128, SEQ / 128, BATCH);               // (8, 16, 4)
    pv_mma<<<g4, 256, SMEM_BYTES>>>(out);
}